// round 10
// baseline (speedup 1.0000x reference)
#include <cuda_runtime.h>
#include <math.h>

#define NB 2
#define LQ 2048
#define SQ 2048
#define HH 8
#define EE 64
#define DD 64
#define CC 256
#define KK 32
#define NH (NB*HH)
#define TEMP 0.125f
#define SCL 0.18033688011112042f   /* TEMP * log2(e) */

// packed fp32x2 FMA (FFMA2) — ptxas never emits this from C++
__device__ __forceinline__ void fma2(unsigned long long &d, unsigned long long a,
                                     unsigned long long b) {
    asm("fma.rn.f32x2 %0, %1, %2, %3;" : "=l"(d) : "l"(a), "l"(b), "l"(d));
}
__device__ __forceinline__ float2 upk(unsigned long long v) {
    float2 r; asm("mov.b64 {%0,%1}, %2;" : "=f"(r.x), "=f"(r.y) : "l"(v)); return r;
}

// ---------------- scratch (device globals; no allocation allowed) ----------
__device__ float g_Qg[NH*CC*EE];        // per-cluster mean queries
__device__ int   g_qcnt[NH*CC];         // cluster counts
__device__ float g_probs[NH*CC*SQ];     // scaled logits (log2 domain, no max-shift)
__device__ float g_Vbtm[NH*CC*DD];      // FULL softmax-weighted V per cluster
__device__ float g_Ab[NH*CC];           // top-k probability mass
__device__ float g_B[NH*CC];            // exp2 bias: log2(invZ)
__device__ int   g_topk[NH*CC*KK];      // top-k key indices per cluster
__device__ float g_topkp[NH*CC*KK];     // top-k probabilities per cluster
__device__ int   g_qoff[NH*CC + 1];     // query-list offsets per cluster
__device__ int   g_qcur[NH*CC];         // scatter cursors
__device__ int   g_qlist[NH*LQ];        // query l-indices grouped by cluster

// ---------------- zero Vbtm + counts ----------------------------------------
__global__ void k_zero() {
    int i = blockIdx.x * blockDim.x + threadIdx.x;   // NH*CC*DD threads
    g_Vbtm[i] = 0.f;
    if (i < NH*CC) g_qcnt[i] = 0;
}

// ---------------- count queries per cluster ---------------------------------
__global__ void k_count(const int* __restrict__ cid) {
    int t = blockIdx.x * blockDim.x + threadIdx.x;   // NH*LQ threads
    if (t >= NH*LQ) return;
    atomicAdd(&g_qcnt[(t / LQ)*CC + __ldg(&cid[t])], 1);
}

// ---------------- exclusive scan of 4096 counts (1 block, 256 thr) ----------
__global__ void k_scan() {
    __shared__ int wsum[8];
    const int t = threadIdx.x, lane = t & 31, wid = t >> 5;
    int c[16], tot = 0;
    #pragma unroll
    for (int j = 0; j < 16; j++) { c[j] = g_qcnt[t*16 + j]; tot += c[j]; }
    int inc = tot;
    #pragma unroll
    for (int o = 1; o < 32; o <<= 1) {
        int x = __shfl_up_sync(~0u, inc, o);
        if (lane >= o) inc += x;
    }
    if (lane == 31) wsum[wid] = inc;
    __syncthreads();
    if (t < 8) {
        int v = wsum[t];
        #pragma unroll
        for (int o = 1; o < 8; o <<= 1) {
            int x = __shfl_up_sync(0xffu, v, o);
            if (t >= o) v += x;
        }
        wsum[t] = v;
    }
    __syncthreads();
    int ex = (wid ? wsum[wid-1] : 0) + inc - tot;
    #pragma unroll
    for (int j = 0; j < 16; j++) {
        g_qoff[t*16 + j] = ex;
        g_qcur[t*16 + j] = ex;
        ex += c[j];
    }
    if (t == 255) g_qoff[NH*CC] = ex;
}

// ---------------- scatter query indices into cluster-grouped lists ----------
__global__ void k_scatter(const int* __restrict__ cid) {
    int t = blockIdx.x * blockDim.x + threadIdx.x;
    if (t >= NH*LQ) return;
    int l  = t % LQ;
    int nh = t / LQ;
    int c  = __ldg(&cid[nh*LQ + l]);
    int pos = atomicAdd(&g_qcur[nh*CC + c], 1);
    g_qlist[pos] = l;
}

// ---------------- per-cluster query mean (warp per cluster, no atomics) -----
__global__ void k_qg(const float* __restrict__ q) {
    const int b = blockIdx.x*8 + (threadIdx.x >> 5);  // nh*CC + c
    const int lane = threadIdx.x & 31;
    const int nh = b >> 8, n = nh >> 3, h = nh & 7;
    const int q0 = g_qoff[b], q1 = g_qoff[b + 1];
    float a0 = 0.f, a1 = 0.f;
    for (int qi = q0; qi < q1; qi++) {
        const int l = g_qlist[qi];
        const float* qr = q + (size_t)((n*LQ + l)*HH + h)*EE;
        a0 += __ldg(qr + lane);
        a1 += __ldg(qr + lane + 32);
    }
    const float inv = 1.f / fmaxf((float)(q1 - q0), 1.f);
    g_Qg[b*EE + lane]      = a0 * inv;
    g_Qg[b*EE + lane + 32] = a1 * inv;
}

// ---------------- QK GEMM: 64x64 tile, f32x2 over e-pairs -------------------
__global__ void k_qk(const float* __restrict__ keys) {
    __shared__ float4 shQ[64*17];
    __shared__ float4 shK[64*17];
    const int nh = blockIdx.z, n = nh >> 3, h = nh & 7;
    const int c0 = blockIdx.y * 64, s0 = blockIdx.x * 64;
    const int t = threadIdx.x;

    const float* Qb = g_Qg + (nh*CC + c0)*EE;
    #pragma unroll
    for (int r = 0; r < 4; r++) {
        int lin = t + r*256, row = lin >> 4, c4 = lin & 15;
        shQ[row*17 + c4] = *(const float4*)(Qb + row*EE + c4*4);
        shK[row*17 + c4] =
            *(const float4*)(keys + (size_t)((n*SQ + s0 + row)*HH + h)*EE + c4*4);
    }
    __syncthreads();

    const ulonglong2* Qu = (const ulonglong2*)shQ;
    const ulonglong2* Ku = (const ulonglong2*)shK;
    const int tc = t >> 4, ts = t & 15;

    unsigned long long acc2[4][4];
    #pragma unroll
    for (int i = 0; i < 4; i++)
        #pragma unroll
        for (int j = 0; j < 4; j++) acc2[i][j] = 0ull;   // (+0.f, +0.f)

    #pragma unroll
    for (int e4 = 0; e4 < 16; e4++) {
        ulonglong2 a[4], b[4];
        #pragma unroll
        for (int i = 0; i < 4; i++) a[i] = Qu[(tc + i*16)*17 + e4];   // broadcast
        #pragma unroll
        for (int j = 0; j < 4; j++) b[j] = Ku[(ts + j*16)*17 + e4];   // conflict-free
        #pragma unroll
        for (int i = 0; i < 4; i++)
            #pragma unroll
            for (int j = 0; j < 4; j++) {
                fma2(acc2[i][j], a[i].x, b[j].x);
                fma2(acc2[i][j], a[i].y, b[j].y);
            }
    }
    #pragma unroll
    for (int i = 0; i < 4; i++) {
        float* dst = g_probs + (size_t)(nh*CC + c0 + tc + i*16)*SQ + s0 + ts;
        #pragma unroll
        for (int j = 0; j < 4; j++) {
            float2 r = upk(acc2[i][j]);
            dst[j*16] = (r.x + r.y) * SCL;
        }
    }
}

// ---------------- softmax stats + top-32 (no max-shift, cached-best) --------
__global__ void k_stats() {
    __shared__ float    swf[8];
    __shared__ unsigned swu[8];
    __shared__ int      swi_[8];
    __shared__ unsigned s_bu;
    __shared__ int      s_bi;
    const int row = blockIdx.x;
    const int t = threadIdx.x, lane = t & 31, wid = t >> 5;
    const float* P = g_probs + (size_t)row * SQ;

    float v[8];
    float lsum = 0.f;
    #pragma unroll
    for (int j = 0; j < 8; j++) {
        v[j] = P[t + j*256];
        lsum += exp2f(v[j]);
    }
    #pragma unroll
    for (int o = 16; o; o >>= 1) lsum += __shfl_xor_sync(~0u, lsum, o);
    if (lane == 0) swf[wid] = lsum;
    __syncthreads();
    float Z = 0.f;
    #pragma unroll
    for (int w = 0; w < 8; w++) Z += swf[w];
    const float invZ = 1.f / Z;

    unsigned u[8];
    #pragma unroll
    for (int j = 0; j < 8; j++) {
        unsigned b = __float_as_uint(v[j]);
        u[j] = (b & 0x80000000u) ? ~b : (b | 0x80000000u);
    }
    unsigned bu = 0u; int bj = 0;
    #pragma unroll
    for (int j = 0; j < 8; j++) if (u[j] > bu) { bu = u[j]; bj = j; }
    int bidx = t + bj*256;
    {
        unsigned mu = __reduce_max_sync(0xffffffffu, bu);
        unsigned cand = (bu == mu) ? (unsigned)bidx : 0xffffffffu;
        unsigned mi = __reduce_min_sync(0xffffffffu, cand);
        if (lane == 0) { swu[wid] = mu; swi_[wid] = (int)mi; }
    }
    __syncthreads();

    float psum = 0.f;
    for (int it = 0; it < KK; it++) {
        if (t == 0) {
            unsigned Bu = swu[0]; int Bi = swi_[0];
            #pragma unroll
            for (int w = 1; w < 8; w++)
                if (swu[w] > Bu || (swu[w] == Bu && swi_[w] < Bi)) { Bu = swu[w]; Bi = swi_[w]; }
            s_bu = Bu; s_bi = Bi;
            g_topk[row*KK + it] = Bi;
            unsigned fb = (Bu & 0x80000000u) ? (Bu & 0x7fffffffu) : ~Bu;
            float pv = exp2f(__uint_as_float(fb));
            psum += pv;
            g_topkp[row*KK + it] = pv * invZ;
        }
        __syncthreads();
        const int Bi = s_bi;
        const int ot = Bi & 255;
        if (ot == t) {
            u[Bi >> 8] = 0u;
            bu = 0u; bj = 0;
            #pragma unroll
            for (int j = 0; j < 8; j++) if (u[j] > bu) { bu = u[j]; bj = j; }
            bidx = t + bj*256;
        }
        if ((ot >> 5) == wid) {
            unsigned mu = __reduce_max_sync(0xffffffffu, bu);
            unsigned cand = (bu == mu) ? (unsigned)bidx : 0xffffffffu;
            unsigned mi = __reduce_min_sync(0xffffffffu, cand);
            if (lane == 0) { swu[wid] = mu; swi_[wid] = (int)mi; }
        }
        __syncthreads();
    }
    if (t == 0) {
        g_Ab[row] = psum * invZ;
        g_B[row]  = log2f(invZ);
    }
}

// ---------------- V_full = softmax @ V (f32x2 over col-pairs) ---------------
__global__ void k_vbtm(const float* __restrict__ values) {
    __shared__ float2 shPd[64][33];   // duplicated probs (p,p) per [row][s]
    __shared__ float  shV[32][68];
    __shared__ float  sB[64];
    const int nh = blockIdx.z, n = nh >> 3, h = nh & 7;
    const int c0 = blockIdx.y * 64;
    const int sbase = blockIdx.x * 256;
    const int t = threadIdx.x;
    const int tc = t >> 4, ts = t & 15;

    if (t < 64) sB[t] = g_B[nh*CC + c0 + t];
    __syncthreads();

    unsigned long long acc2[4][2];
    #pragma unroll
    for (int i = 0; i < 4; i++) { acc2[i][0] = 0ull; acc2[i][1] = 0ull; }

    for (int ks = 0; ks < 8; ks++) {
        const int s0 = sbase + ks*32;
        #pragma unroll
        for (int r = 0; r < 2; r++) {
            int lin = t + r*256, row = lin >> 3, c4 = lin & 7;
            float4 v = *(const float4*)(g_probs + (size_t)(nh*CC + c0 + row)*SQ + s0 + c4*4);
            float bB = sB[row];
            float px = exp2f(v.x + bB), py = exp2f(v.y + bB);
            float pz = exp2f(v.z + bB), pw = exp2f(v.w + bB);
            shPd[row][c4*4+0] = make_float2(px, px);
            shPd[row][c4*4+1] = make_float2(py, py);
            shPd[row][c4*4+2] = make_float2(pz, pz);
            shPd[row][c4*4+3] = make_float2(pw, pw);
        }
        #pragma unroll
        for (int r = 0; r < 2; r++) {
            int lin = t + r*256, row = lin >> 4, c4 = lin & 15;
            *(float4*)&shV[row][c4*4] =
                *(const float4*)(values + (size_t)((n*SQ + s0 + row)*HH + h)*DD + c4*4);
        }
        __syncthreads();
        #pragma unroll 8
        for (int s = 0; s < 32; s++) {
            ulonglong2 bv = *(const ulonglong2*)&shV[s][ts*4];
            #pragma unroll
            for (int i = 0; i < 4; i++) {
                unsigned long long ai = *(const unsigned long long*)&shPd[tc*4 + i][s];
                fma2(acc2[i][0], ai, bv.x);
                fma2(acc2[i][1], ai, bv.y);
            }
        }
        __syncthreads();
    }
    #pragma unroll
    for (int i = 0; i < 4; i++) {
        float* dst = g_Vbtm + (nh*CC + c0 + tc*4 + i)*DD + ts*4;
        float2 r0 = upk(acc2[i][0]);
        float2 r1 = upk(acc2[i][1]);
        atomicAdd(dst + 0, r0.x);
        atomicAdd(dst + 1, r0.y);
        atomicAdd(dst + 2, r1.x);
        atomicAdd(dst + 3, r1.y);
    }
}

// ---------------- per-cluster final attention (with top-k correction) --------
__global__ void k_final2(const float* __restrict__ q, const float* __restrict__ keys,
                         const float* __restrict__ values, float* __restrict__ out) {
    __shared__ int   s_top[KK];
    __shared__ float s_ptp[KK];
    __shared__ float Ksel[KK][65];
    __shared__ float Vsel[KK][65];
    const int b = blockIdx.x;            // nh*CC + c
    const int nh = b >> 8, n = nh >> 3, h = nh & 7;
    const int t = threadIdx.x, lane = t & 31, wi = t >> 5;

    const int q0 = g_qoff[b];
    const int q1 = g_qoff[b + 1];
    if (q0 == q1) return;

    if (t < KK) { s_top[t] = g_topk[b*KK + t]; s_ptp[t] = g_topkp[b*KK + t]; }
    __syncthreads();

    #pragma unroll
    for (int r = 0; r < 2; r++) {
        int lin = t + r*256;
        int row = lin >> 4, c4 = lin & 15;
        int ki = s_top[row];
        float4 kv = *(const float4*)(keys   + (size_t)((n*SQ + ki)*HH + h)*EE + c4*4);
        float4 vv = *(const float4*)(values + (size_t)((n*SQ + ki)*HH + h)*DD + c4*4);
        Ksel[row][c4*4+0] = kv.x; Ksel[row][c4*4+1] = kv.y;
        Ksel[row][c4*4+2] = kv.z; Ksel[row][c4*4+3] = kv.w;
        Vsel[row][c4*4+0] = vv.x; Vsel[row][c4*4+1] = vv.y;
        Vsel[row][c4*4+2] = vv.z; Vsel[row][c4*4+3] = vv.w;
    }
    __syncthreads();

    const float Ab = __ldg(&g_Ab[b]);
    const float vb0 = __ldg(&g_Vbtm[b*DD + lane]);
    const float vb1 = __ldg(&g_Vbtm[b*DD + lane + 32]);

    for (int qi = q0 + wi; qi < q1; qi += 8) {
        const int l = g_qlist[qi];
        const float* qrow = q + (size_t)((n*LQ + l)*HH + h)*EE;
        const float qv0 = __ldg(qrow + lane);
        const float qv1 = __ldg(qrow + lane + 32);

        float dot = 0.f;
        #pragma unroll
        for (int e = 0; e < 32; e++) {
            float qe = __shfl_sync(~0u, qv0, e);
            dot += qe * Ksel[lane][e];
        }
        #pragma unroll
        for (int e = 0; e < 32; e++) {
            float qe = __shfl_sync(~0u, qv1, e);
            dot += qe * Ksel[lane][e + 32];
        }
        float lg = TEMP * dot;
        float m = lg;
        #pragma unroll
        for (int o = 16; o; o >>= 1) m = fmaxf(m, __shfl_xor_sync(~0u, m, o));
        float p = __expf(lg - m);
        float z = p;
        #pragma unroll
        for (int o = 16; o; o >>= 1) z += __shfl_xor_sync(~0u, z, o);
        const float wk = p * (Ab * __frcp_rn(z));

        float acc0 = vb0, acc1 = vb1;
        #pragma unroll
        for (int k = 0; k < KK; k++) {
            float wv = __shfl_sync(~0u, wk, k) - s_ptp[k];
            acc0 += wv * Vsel[k][lane];
            acc1 += wv * Vsel[k][lane + 32];
        }
        float* orow = out + (size_t)((n*LQ + l)*HH + h)*DD;
        orow[lane]      = acc0;
        orow[lane + 32] = acc1;
    }
}

// ---------------- launch -----------------------------------------------------
extern "C" void kernel_launch(void* const* d_in, const int* in_sizes, int n_in,
                              void* d_out, int out_size) {
    const float* queries = (const float*)d_in[0];
    const float* keys    = (const float*)d_in[1];
    const float* values  = (const float*)d_in[2];
    const int*   cids    = (const int*)d_in[3];
    float* out = (float*)d_out;

    k_zero<<<NH*CC*DD/256, 256>>>();
    k_count<<<(NH*LQ + 255)/256, 256>>>(cids);
    k_scan<<<1, 256>>>();
    k_scatter<<<(NH*LQ + 255)/256, 256>>>(cids);
    k_qg<<<NH*CC/8, 256>>>(queries);

    dim3 gB(SQ/64, CC/64, NH);
    k_qk<<<gB, 256>>>(keys);

    k_stats<<<NH*CC, 256>>>();

    dim3 gD(8, CC/64, NH);
    k_vbtm<<<gD, 256>>>(values);

    k_final2<<<NH*CC, 256>>>(queries, keys, values, out);
}